// round 9
// baseline (speedup 1.0000x reference)
#include <cuda_runtime.h>
#include <math_constants.h>
#include <cstdint>

// Problem: B=4, T=4096, C=1024, H=64. Causal single-head attention.
// out = softmax(mask(scale * (x@Wq)(x@Wk)^T)) @ (x@Wv)

#define B_  4
#define T_  4096
#define C_  1024
#define H_  64
#define SCALE 0.125f   // 64^-0.5, folded into Wq during prep (exact pow2)

// tf32 hi/lo split storage (written by proj, read by attn)
__device__ __align__(16) float2 g_qhl[B_ * T_ * H_];   // [b*T+t][h] (q pre-scaled)
__device__ __align__(16) float2 g_khl[B_ * T_ * H_];   // [b*T+t][h]
__device__ __align__(16) float2 g_vT [B_ * H_ * T_];   // [b][h][t]  (transposed)
__device__ __align__(16) float2 g_wt [3 * H_ * C_];    // [p][n][k], 0=q(scaled),1=k,2=v

// ---------------------------------------------------------------------------
// helpers
// ---------------------------------------------------------------------------
__device__ __forceinline__ uint32_t cvt_tf32(float x) {
    uint32_t r;
    asm("cvt.rna.tf32.f32 %0, %1;" : "=r"(r) : "f"(x));
    return r;
}
__device__ __forceinline__ float2 split2(float x) {
    uint32_t hi = cvt_tf32(x);
    float fhi = __uint_as_float(hi);
    uint32_t lo = cvt_tf32(x - fhi);
    return make_float2(fhi, __uint_as_float(lo));
}
__device__ __forceinline__ void mma8(float c[4], const uint32_t a[4],
                                     uint32_t b0, uint32_t b1) {
    asm volatile(
        "mma.sync.aligned.m16n8k8.row.col.f32.tf32.tf32.f32 "
        "{%0,%1,%2,%3}, {%4,%5,%6,%7}, {%8,%9}, {%0,%1,%2,%3};\n"
        : "+f"(c[0]), "+f"(c[1]), "+f"(c[2]), "+f"(c[3])
        : "r"(a[0]), "r"(a[1]), "r"(a[2]), "r"(a[3]), "r"(b0), "r"(b1));
}
__device__ __forceinline__ uint32_t sptr(const void* p) {
    return (uint32_t)__cvta_generic_to_shared(p);
}
__device__ __forceinline__ void cp16(uint32_t s, const void* g) {
    asm volatile("cp.async.cg.shared.global [%0], [%1], 16;" :: "r"(s), "l"(g));
}
#define CP_COMMIT() asm volatile("cp.async.commit_group;")
#define CP_WAIT0()  asm volatile("cp.async.wait_group 0;" ::: "memory")

// ---------------------------------------------------------------------------
// prep: split W into tf32 hi/lo, transposed [n][k]; fold SCALE into Wq.
// ---------------------------------------------------------------------------
__global__ void prep_w(const float* __restrict__ Wq,
                       const float* __restrict__ Wk,
                       const float* __restrict__ Wv)
{
    int idx = blockIdx.x * 256 + threadIdx.x;     // 0..196607
    int p = idx >> 16;
    int r = idx & 65535;
    int k = r >> 6;
    int n = r & 63;
    const float* W = (p == 0) ? Wq : (p == 1 ? Wk : Wv);
    float v = W[k * 64 + n];
    if (p == 0) v *= SCALE;
    g_wt[p * 65536 + n * 1024 + k] = split2(v);
}

// ---------------------------------------------------------------------------
// Projection, 3xTF32 tensor cores, fused q/k/v.
// Block: 256 thr (8 warps), M=128 x N=192. Both x and W smem double-buffered:
// ONE __syncthreads per 32-wide k-chunk.
// ---------------------------------------------------------------------------
#define PW 34   // float2 row stride for 32-k chunks

__global__ __launch_bounds__(256)
void proj_kernel(const float* __restrict__ x)
{
    extern __shared__ float2 psm[];
    float2* xs0 = psm;                  // [128][34]
    float2* xs1 = xs0 + 128 * PW;
    float2* ws0 = xs1 + 128 * PW;       // [192][34]
    float2* ws1 = ws0 + 192 * PW;

    const int tid  = threadIdx.x;
    const int wid  = tid >> 5;
    const int lane = tid & 31;
    const int g    = lane >> 2;
    const int tig  = lane & 3;
    const int m0   = blockIdx.x * 128;
    const int rlo  = wid * 16 + g;
    const int rhi  = rlo + 8;

    float c[24][4];
#pragma unroll
    for (int f = 0; f < 24; f++)
#pragma unroll
        for (int j = 0; j < 4; j++) c[f][j] = 0.f;

    const int xrow = tid >> 1, xhalf = tid & 1;
    const float* xptr = x + (size_t)(m0 + xrow) * C_ + xhalf * 16;

    // prologue: x chunk 0 -> regs
    float4 xpre[4];
#pragma unroll
    for (int j = 0; j < 4; j++) xpre[j] = *(const float4*)(xptr + j * 4);

    // W chunk 0 -> ws0 (cp.async)
#pragma unroll
    for (int i = 0; i < 12; i++) {
        int idx = tid + i * 256;           // 0..3071
        int n = idx >> 4, kp = idx & 15;
        cp16(sptr(ws0 + n * PW + kp * 2), g_wt + (size_t)n * 1024 + kp * 2);
    }
    CP_COMMIT();

    // split & store chunk 0 -> xs0; then load chunk 1 -> regs
#pragma unroll
    for (int j = 0; j < 4; j++) {
        float2 e0 = split2(xpre[j].x);
        float2 e1 = split2(xpre[j].y);
        float2 e2 = split2(xpre[j].z);
        float2 e3 = split2(xpre[j].w);
        float4* d = (float4*)(xs0 + xrow * PW + xhalf * 16 + j * 4);
        d[0] = make_float4(e0.x, e0.y, e1.x, e1.y);
        d[1] = make_float4(e2.x, e2.y, e3.x, e3.y);
    }
#pragma unroll
    for (int j = 0; j < 4; j++) xpre[j] = *(const float4*)(xptr + 32 + j * 4);

    for (int kc = 0; kc < 32; kc++) {
        const float2* xs = (kc & 1) ? xs1 : xs0;
        const float2* ws = (kc & 1) ? ws1 : ws0;
        CP_WAIT0();
        __syncthreads();   // ws[kc], xs[kc] ready; other buffers' consumers done

        if (kc + 1 < 32) {
            float2* wsn = (kc & 1) ? ws0 : ws1;
#pragma unroll
            for (int i = 0; i < 12; i++) {
                int idx = tid + i * 256;
                int n = idx >> 4, kp = idx & 15;
                cp16(sptr(wsn + n * PW + kp * 2),
                     g_wt + (size_t)n * 1024 + (kc + 1) * 32 + kp * 2);
            }
            CP_COMMIT();
            float2* xsn = (kc & 1) ? xs0 : xs1;
#pragma unroll
            for (int j = 0; j < 4; j++) {
                float2 e0 = split2(xpre[j].x);
                float2 e1 = split2(xpre[j].y);
                float2 e2 = split2(xpre[j].z);
                float2 e3 = split2(xpre[j].w);
                float4* d = (float4*)(xsn + xrow * PW + xhalf * 16 + j * 4);
                d[0] = make_float4(e0.x, e0.y, e1.x, e1.y);
                d[1] = make_float4(e2.x, e2.y, e3.x, e3.y);
            }
            if (kc + 2 < 32) {
                const float* xn = xptr + (kc + 2) * 32;
#pragma unroll
                for (int j = 0; j < 4; j++) xpre[j] = *(const float4*)(xn + j * 4);
            }
        }

#pragma unroll
        for (int k0 = 0; k0 < 32; k0 += 8) {
            uint32_t ahi[4], alo[4];
            {
                uint2 t;
                t = *(const uint2*)&xs[rlo * PW + k0 + tig];     ahi[0] = t.x; alo[0] = t.y;
                t = *(const uint2*)&xs[rhi * PW + k0 + tig];     ahi[1] = t.x; alo[1] = t.y;
                t = *(const uint2*)&xs[rlo * PW + k0 + tig + 4]; ahi[2] = t.x; alo[2] = t.y;
                t = *(const uint2*)&xs[rhi * PW + k0 + tig + 4]; ahi[3] = t.x; alo[3] = t.y;
            }
#pragma unroll
            for (int f = 0; f < 24; f++) {
                uint2 b0 = *(const uint2*)&ws[(f * 8 + g) * PW + k0 + tig];
                uint2 b1 = *(const uint2*)&ws[(f * 8 + g) * PW + k0 + tig + 4];
                mma8(c[f], ahi, b0.x, b1.x);
                mma8(c[f], ahi, b0.y, b1.y);
                mma8(c[f], alo, b0.x, b1.x);
            }
        }
    }

    // epilogue: split accumulators, write hi/lo
#pragma unroll
    for (int f = 0; f < 24; f++) {
        int p  = f >> 3;
        int hh = (f & 7) * 8 + tig * 2;
        float2 e0 = split2(c[f][0]);
        float2 e1 = split2(c[f][1]);
        float2 e2 = split2(c[f][2]);
        float2 e3 = split2(c[f][3]);
        if (p < 2) {
            float2* basep = (p == 0) ? g_qhl : g_khl;
            *(float4*)(basep + (size_t)(m0 + rlo) * 64 + hh) =
                make_float4(e0.x, e0.y, e1.x, e1.y);
            *(float4*)(basep + (size_t)(m0 + rhi) * 64 + hh) =
                make_float4(e2.x, e2.y, e3.x, e3.y);
        } else {
            int r0g = m0 + rlo, bb0 = r0g >> 12, t0 = r0g & 4095;
            int r1g = m0 + rhi, bb1 = r1g >> 12, t1 = r1g & 4095;
            g_vT[(size_t)bb0 * 262144 + (size_t)hh * 4096 + t0]       = e0;
            g_vT[(size_t)bb0 * 262144 + (size_t)(hh + 1) * 4096 + t0] = e1;
            g_vT[(size_t)bb1 * 262144 + (size_t)hh * 4096 + t1]       = e2;
            g_vT[(size_t)bb1 * 262144 + (size_t)(hh + 1) * 4096 + t1] = e3;
        }
    }
}

// ---------------------------------------------------------------------------
// Flash attention (causal), tensor cores. 128 threads = 4 warps; each warp
// owns FULL rows: m16 x n64 warp tile -> softmax entirely warp-local, P stays
// in registers (C-frag -> A-frag quad-shuffle permute). One __syncthreads per
// tile (KV double-buffer publish). Q frags direct from gmem. AS=66: the 8
// g-rows of every b-frag uint2 load hit 8 distinct banks (68 had 2-way).
// Pair schedule (i, 63-i): 65 tiles per block. Grid (32, B).
// ---------------------------------------------------------------------------
#define AS 66    // float2 row stride

__device__ __forceinline__ void issue_kv(const float2* kb, const float2* vb,
                                         int jt, float2* Ks, float2* Vt, int tid)
{
#pragma unroll
    for (int i = 0; i < 16; i++) {
        int c = tid + i * 128;            // 0..2047
        int r = c >> 5, q = c & 31;
        cp16(sptr(Ks + r * AS + q * 2), kb + (size_t)(jt * 64 + r) * 64 + q * 2);
        cp16(sptr(Vt + r * AS + q * 2), vb + (size_t)r * 4096 + jt * 64 + q * 2);
    }
}

__global__ __launch_bounds__(128)
void attn_kernel(float* __restrict__ out)
{
    extern __shared__ float2 smp[];
    float2* Ks0 = smp;
    float2* Vt0 = Ks0 + 64 * AS;
    float2* Ks1 = Vt0 + 64 * AS;
    float2* Vt1 = Ks1 + 64 * AS;

    const int b    = blockIdx.y;
    const int pair = blockIdx.x;
    const int tid  = threadIdx.x;
    const int wid  = tid >> 5;        // 0..3
    const int lane = tid & 31;
    const int g    = lane >> 2;
    const int tig  = lane & 3;
    const int rlo  = wid * 16 + g;    // local q row (c0/c1)
    const int rhi  = rlo + 8;         // local q row (c2/c3)
    const int src0 = (lane & 28) | (tig >> 1);   // quad lane holding col tig
    const int src1 = src0 + 2;                   // quad lane holding col tig+4

    const float2* kb = g_khl + (size_t)b * T_ * 64;
    const float2* vb = g_vT  + (size_t)b * 64 * T_;
    const float2* qb = g_qhl + (size_t)b * T_ * 64;

    for (int side = 0; side < 2; side++) {
        const int qt = side ? (63 - pair) : pair;
        const int q0 = qt * 64;
        const int ntile = qt + 1;

        __syncthreads();   // prior side's KV consumers done

        // Q fragments straight from gmem (hi,lo interleaved float2)
        uint32_t qhi[8][4], qlo[8][4];
        {
            const uint2* qr0 = (const uint2*)(qb + (size_t)(q0 + rlo) * 64);
            const uint2* qr1 = (const uint2*)(qb + (size_t)(q0 + rhi) * 64);
#pragma unroll
            for (int i = 0; i < 8; i++) {
                uint2 t;
                t = qr0[8 * i + tig];     qhi[i][0] = t.x; qlo[i][0] = t.y;
                t = qr1[8 * i + tig];     qhi[i][1] = t.x; qlo[i][1] = t.y;
                t = qr0[8 * i + tig + 4]; qhi[i][2] = t.x; qlo[i][2] = t.y;
                t = qr1[8 * i + tig + 4]; qhi[i][3] = t.x; qlo[i][3] = t.y;
            }
        }

        issue_kv(kb, vb, 0, Ks0, Vt0, tid);
        CP_COMMIT();

        float m0v = -CUDART_INF_F, m1v = -CUDART_INF_F;
        float l0v = 0.f, l1v = 0.f;
        float o[8][4];
#pragma unroll
        for (int f = 0; f < 8; f++)
#pragma unroll
            for (int j = 0; j < 4; j++) o[f][j] = 0.f;

        for (int jt = 0; jt < ntile; jt++) {
            CP_WAIT0();
            __syncthreads();   // KV[jt&1] visible block-wide; other buffer free

            const float2* Kst = (jt & 1) ? Ks1 : Ks0;
            const float2* Vtt = (jt & 1) ? Vt1 : Vt0;
            if (jt + 1 < ntile) {
                issue_kv(kb, vb, jt + 1, (jt & 1) ? Ks0 : Ks1,
                         (jt & 1) ? Vt0 : Vt1, tid);
                CP_COMMIT();
            }

            // ---- S = Q.K^T (3xTF32), warp tile m16 x n64
            float s[8][4];
#pragma unroll
            for (int f = 0; f < 8; f++)
#pragma unroll
                for (int j = 0; j < 4; j++) s[f][j] = 0.f;

#pragma unroll
            for (int i = 0; i < 8; i++) {
#pragma unroll
                for (int f = 0; f < 8; f++) {
                    uint2 u0 = *(const uint2*)&Kst[(8 * f + g) * AS + 8 * i + tig];
                    uint2 u1 = *(const uint2*)&Kst[(8 * f + g) * AS + 8 * i + tig + 4];
                    mma8(s[f], qhi[i], u0.x, u1.x);
                    mma8(s[f], qhi[i], u0.y, u1.y);
                    mma8(s[f], qlo[i], u0.x, u1.x);
                }
            }

            // ---- causal mask (diagonal tile only; scale pre-folded)
            if (jt == ntile - 1) {
                const int rglo = q0 + rlo, rghi = q0 + rhi;
                const int cb = jt * 64;
#pragma unroll
                for (int f = 0; f < 8; f++) {
                    int c0 = cb + 8 * f + 2 * tig;
                    if (c0 > rglo)     s[f][0] = -1e30f;
                    if (c0 + 1 > rglo) s[f][1] = -1e30f;
                    if (c0 > rghi)     s[f][2] = -1e30f;
                    if (c0 + 1 > rghi) s[f][3] = -1e30f;
                }
            }

            // ---- row max (warp-local: quad shuffle)
            float pmlo = -CUDART_INF_F, pmhi = -CUDART_INF_F;
#pragma unroll
            for (int f = 0; f < 8; f++) {
                pmlo = fmaxf(pmlo, fmaxf(s[f][0], s[f][1]));
                pmhi = fmaxf(pmhi, fmaxf(s[f][2], s[f][3]));
            }
            pmlo = fmaxf(pmlo, __shfl_xor_sync(0xffffffffu, pmlo, 1));
            pmlo = fmaxf(pmlo, __shfl_xor_sync(0xffffffffu, pmlo, 2));
            pmhi = fmaxf(pmhi, __shfl_xor_sync(0xffffffffu, pmhi, 1));
            pmhi = fmaxf(pmhi, __shfl_xor_sync(0xffffffffu, pmhi, 2));

            const float mn0 = fmaxf(m0v, pmlo);
            const float mn1 = fmaxf(m1v, pmhi);
            const float a0  = __expf(m0v - mn0);
            const float a1  = __expf(m1v - mn1);
            m0v = mn0; m1v = mn1;

            // ---- p = exp(s - m), partial l, rescale O
            float ps0 = 0.f, ps1 = 0.f;
#pragma unroll
            for (int f = 0; f < 8; f++) {
                s[f][0] = __expf(s[f][0] - mn0);
                s[f][1] = __expf(s[f][1] - mn0);
                s[f][2] = __expf(s[f][2] - mn1);
                s[f][3] = __expf(s[f][3] - mn1);
                ps0 += s[f][0] + s[f][1];
                ps1 += s[f][2] + s[f][3];
            }
            ps0 += __shfl_xor_sync(0xffffffffu, ps0, 1);
            ps0 += __shfl_xor_sync(0xffffffffu, ps0, 2);
            ps1 += __shfl_xor_sync(0xffffffffu, ps1, 1);
            ps1 += __shfl_xor_sync(0xffffffffu, ps1, 2);
            l0v = l0v * a0 + ps0;
            l1v = l1v * a1 + ps1;
#pragma unroll
            for (int f = 0; f < 8; f++) {
                o[f][0] *= a0; o[f][1] *= a0;
                o[f][2] *= a1; o[f][3] *= a1;
            }

            // ---- O += P.V : per k-chunk, permute P C-frag -> A-frag via quad
            //      shuffles (tf32 once; same value summed into l above pre-cvt)
#pragma unroll
            for (int f = 0; f < 8; f++) {
                uint32_t u0 = cvt_tf32(s[f][0]);
                uint32_t u1 = cvt_tf32(s[f][1]);
                uint32_t u2 = cvt_tf32(s[f][2]);
                uint32_t u3 = cvt_tf32(s[f][3]);
                uint32_t pa[4];
                {
                    uint32_t x0 = __shfl_sync(0xffffffffu, u0, src0);
                    uint32_t x1 = __shfl_sync(0xffffffffu, u1, src0);
                    pa[0] = (tig & 1) ? x1 : x0;          // (rlo, col tig)
                    uint32_t y0 = __shfl_sync(0xffffffffu, u2, src0);
                    uint32_t y1 = __shfl_sync(0xffffffffu, u3, src0);
                    pa[1] = (tig & 1) ? y1 : y0;          // (rhi, col tig)
                    uint32_t z0 = __shfl_sync(0xffffffffu, u0, src1);
                    uint32_t z1 = __shfl_sync(0xffffffffu, u1, src1);
                    pa[2] = (tig & 1) ? z1 : z0;          // (rlo, col tig+4)
                    uint32_t w0 = __shfl_sync(0xffffffffu, u2, src1);
                    uint32_t w1 = __shfl_sync(0xffffffffu, u3, src1);
                    pa[3] = (tig & 1) ? w1 : w0;          // (rhi, col tig+4)
                }
#pragma unroll
                for (int fo = 0; fo < 8; fo++) {
                    uint2 v0 = *(const uint2*)&Vtt[(8 * fo + g) * AS + 8 * f + tig];
                    uint2 v1 = *(const uint2*)&Vtt[(8 * fo + g) * AS + 8 * f + tig + 4];
                    mma8(o[fo], pa, v0.x, v1.x);
                    mma8(o[fo], pa, v0.y, v1.y);
                }
            }
        }

        // ---- epilogue (l warp-local, replicated across quad)
        {
            const float inv0 = 1.f / l0v;
            const float inv1 = 1.f / l1v;
            float* or0 = out + ((size_t)b * T_ + q0 + rlo) * H_;
            float* or1 = out + ((size_t)b * T_ + q0 + rhi) * H_;
#pragma unroll
            for (int f = 0; f < 8; f++) {
                int cc = 8 * f + 2 * tig;
                *(float2*)&or0[cc] = make_float2(o[f][0] * inv0, o[f][1] * inv0);
                *(float2*)&or1[cc] = make_float2(o[f][2] * inv1, o[f][3] * inv1);
            }
        }
    }
}

// ---------------------------------------------------------------------------

extern "C" void kernel_launch(void* const* d_in, const int* in_sizes, int n_in,
                              void* d_out, int out_size)
{
    const float* x  = (const float*)d_in[0];
    const float* Wk = (const float*)d_in[1];
    const float* Wq = (const float*)d_in[2];
    const float* Wv = (const float*)d_in[3];
    float* out = (float*)d_out;

    prep_w<<<768, 256>>>(Wq, Wk, Wv);

    const int psmem = (2 * 128 * PW + 2 * 192 * PW) * (int)sizeof(float2); // 174080
    cudaFuncSetAttribute(proj_kernel, cudaFuncAttributeMaxDynamicSharedMemorySize, psmem);
    proj_kernel<<<128, 256, psmem>>>(x);

    const int asmem = 4 * 64 * AS * (int)sizeof(float2); // 135168
    cudaFuncSetAttribute(attn_kernel, cudaFuncAttributeMaxDynamicSharedMemorySize, asmem);
    attn_kernel<<<dim3(32, B_), 128, asmem>>>(out);
}

// round 10
// speedup vs baseline: 1.2444x; 1.2444x over previous
#include <cuda_runtime.h>
#include <math_constants.h>
#include <cstdint>

// Problem: B=4, T=4096, C=1024, H=64. Causal single-head attention.
// out = softmax(mask(scale * (x@Wq)(x@Wk)^T)) @ (x@Wv)

#define B_  4
#define T_  4096
#define C_  1024
#define H_  64
#define SCALE 0.125f   // 64^-0.5, folded into Wq during prep (exact pow2)

// tf32 hi/lo split storage (written by proj, read by attn)
__device__ __align__(16) float2 g_qhl[B_ * T_ * H_];   // [b*T+t][h] (q pre-scaled)
__device__ __align__(16) float2 g_khl[B_ * T_ * H_];   // [b*T+t][h]
__device__ __align__(16) float2 g_vT [B_ * H_ * T_];   // [b][h][t]  (transposed)
__device__ __align__(16) float2 g_wt [3 * H_ * C_];    // [p][n][k], 0=q(scaled),1=k,2=v

// ---------------------------------------------------------------------------
// helpers
// ---------------------------------------------------------------------------
__device__ __forceinline__ uint32_t cvt_tf32(float x) {
    uint32_t r;
    asm("cvt.rna.tf32.f32 %0, %1;" : "=r"(r) : "f"(x));
    return r;
}
__device__ __forceinline__ float2 split2(float x) {
    uint32_t hi = cvt_tf32(x);
    float fhi = __uint_as_float(hi);
    uint32_t lo = cvt_tf32(x - fhi);
    return make_float2(fhi, __uint_as_float(lo));
}
__device__ __forceinline__ void mma8(float c[4], const uint32_t a[4],
                                     uint32_t b0, uint32_t b1) {
    asm volatile(
        "mma.sync.aligned.m16n8k8.row.col.f32.tf32.tf32.f32 "
        "{%0,%1,%2,%3}, {%4,%5,%6,%7}, {%8,%9}, {%0,%1,%2,%3};\n"
        : "+f"(c[0]), "+f"(c[1]), "+f"(c[2]), "+f"(c[3])
        : "r"(a[0]), "r"(a[1]), "r"(a[2]), "r"(a[3]), "r"(b0), "r"(b1));
}
__device__ __forceinline__ uint32_t sptr(const void* p) {
    return (uint32_t)__cvta_generic_to_shared(p);
}
__device__ __forceinline__ void cp16(uint32_t s, const void* g) {
    asm volatile("cp.async.cg.shared.global [%0], [%1], 16;" :: "r"(s), "l"(g));
}
#define CP_COMMIT() asm volatile("cp.async.commit_group;")
#define CP_WAIT0()  asm volatile("cp.async.wait_group 0;" ::: "memory")

// ---------------------------------------------------------------------------
// prep: split W into tf32 hi/lo, transposed [n][k]; fold SCALE into Wq.
// ---------------------------------------------------------------------------
__global__ void prep_w(const float* __restrict__ Wq,
                       const float* __restrict__ Wk,
                       const float* __restrict__ Wv)
{
    int idx = blockIdx.x * 256 + threadIdx.x;     // 0..196607
    int p = idx >> 16;
    int r = idx & 65535;
    int k = r >> 6;
    int n = r & 63;
    const float* W = (p == 0) ? Wq : (p == 1 ? Wk : Wv);
    float v = W[k * 64 + n];
    if (p == 0) v *= SCALE;
    g_wt[p * 65536 + n * 1024 + k] = split2(v);
}

// ---------------------------------------------------------------------------
// Projection, 3xTF32 tensor cores, fused q/k/v. (unchanged from R9 — passed)
// ---------------------------------------------------------------------------
#define PW 34   // float2 row stride for 32-k chunks

__global__ __launch_bounds__(256)
void proj_kernel(const float* __restrict__ x)
{
    extern __shared__ float2 psm[];
    float2* xs0 = psm;                  // [128][34]
    float2* xs1 = xs0 + 128 * PW;
    float2* ws0 = xs1 + 128 * PW;       // [192][34]
    float2* ws1 = ws0 + 192 * PW;

    const int tid  = threadIdx.x;
    const int wid  = tid >> 5;
    const int lane = tid & 31;
    const int g    = lane >> 2;
    const int tig  = lane & 3;
    const int m0   = blockIdx.x * 128;
    const int rlo  = wid * 16 + g;
    const int rhi  = rlo + 8;

    float c[24][4];
#pragma unroll
    for (int f = 0; f < 24; f++)
#pragma unroll
        for (int j = 0; j < 4; j++) c[f][j] = 0.f;

    const int xrow = tid >> 1, xhalf = tid & 1;
    const float* xptr = x + (size_t)(m0 + xrow) * C_ + xhalf * 16;

    float4 xpre[4];
#pragma unroll
    for (int j = 0; j < 4; j++) xpre[j] = *(const float4*)(xptr + j * 4);

#pragma unroll
    for (int i = 0; i < 12; i++) {
        int idx = tid + i * 256;
        int n = idx >> 4, kp = idx & 15;
        cp16(sptr(ws0 + n * PW + kp * 2), g_wt + (size_t)n * 1024 + kp * 2);
    }
    CP_COMMIT();

#pragma unroll
    for (int j = 0; j < 4; j++) {
        float2 e0 = split2(xpre[j].x);
        float2 e1 = split2(xpre[j].y);
        float2 e2 = split2(xpre[j].z);
        float2 e3 = split2(xpre[j].w);
        float4* d = (float4*)(xs0 + xrow * PW + xhalf * 16 + j * 4);
        d[0] = make_float4(e0.x, e0.y, e1.x, e1.y);
        d[1] = make_float4(e2.x, e2.y, e3.x, e3.y);
    }
#pragma unroll
    for (int j = 0; j < 4; j++) xpre[j] = *(const float4*)(xptr + 32 + j * 4);

    for (int kc = 0; kc < 32; kc++) {
        const float2* xs = (kc & 1) ? xs1 : xs0;
        const float2* ws = (kc & 1) ? ws1 : ws0;
        CP_WAIT0();
        __syncthreads();

        if (kc + 1 < 32) {
            float2* wsn = (kc & 1) ? ws0 : ws1;
#pragma unroll
            for (int i = 0; i < 12; i++) {
                int idx = tid + i * 256;
                int n = idx >> 4, kp = idx & 15;
                cp16(sptr(wsn + n * PW + kp * 2),
                     g_wt + (size_t)n * 1024 + (kc + 1) * 32 + kp * 2);
            }
            CP_COMMIT();
            float2* xsn = (kc & 1) ? xs0 : xs1;
#pragma unroll
            for (int j = 0; j < 4; j++) {
                float2 e0 = split2(xpre[j].x);
                float2 e1 = split2(xpre[j].y);
                float2 e2 = split2(xpre[j].z);
                float2 e3 = split2(xpre[j].w);
                float4* d = (float4*)(xsn + xrow * PW + xhalf * 16 + j * 4);
                d[0] = make_float4(e0.x, e0.y, e1.x, e1.y);
                d[1] = make_float4(e2.x, e2.y, e3.x, e3.y);
            }
            if (kc + 2 < 32) {
                const float* xn = xptr + (kc + 2) * 32;
#pragma unroll
                for (int j = 0; j < 4; j++) xpre[j] = *(const float4*)(xn + j * 4);
            }
        }

#pragma unroll
        for (int k0 = 0; k0 < 32; k0 += 8) {
            uint32_t ahi[4], alo[4];
            {
                uint2 t;
                t = *(const uint2*)&xs[rlo * PW + k0 + tig];     ahi[0] = t.x; alo[0] = t.y;
                t = *(const uint2*)&xs[rhi * PW + k0 + tig];     ahi[1] = t.x; alo[1] = t.y;
                t = *(const uint2*)&xs[rlo * PW + k0 + tig + 4]; ahi[2] = t.x; alo[2] = t.y;
                t = *(const uint2*)&xs[rhi * PW + k0 + tig + 4]; ahi[3] = t.x; alo[3] = t.y;
            }
#pragma unroll
            for (int f = 0; f < 24; f++) {
                uint2 b0 = *(const uint2*)&ws[(f * 8 + g) * PW + k0 + tig];
                uint2 b1 = *(const uint2*)&ws[(f * 8 + g) * PW + k0 + tig + 4];
                mma8(c[f], ahi, b0.x, b1.x);
                mma8(c[f], ahi, b0.y, b1.y);
                mma8(c[f], alo, b0.x, b1.x);
            }
        }
    }

#pragma unroll
    for (int f = 0; f < 24; f++) {
        int p  = f >> 3;
        int hh = (f & 7) * 8 + tig * 2;
        float2 e0 = split2(c[f][0]);
        float2 e1 = split2(c[f][1]);
        float2 e2 = split2(c[f][2]);
        float2 e3 = split2(c[f][3]);
        if (p < 2) {
            float2* basep = (p == 0) ? g_qhl : g_khl;
            *(float4*)(basep + (size_t)(m0 + rlo) * 64 + hh) =
                make_float4(e0.x, e0.y, e1.x, e1.y);
            *(float4*)(basep + (size_t)(m0 + rhi) * 64 + hh) =
                make_float4(e2.x, e2.y, e3.x, e3.y);
        } else {
            int r0g = m0 + rlo, bb0 = r0g >> 12, t0 = r0g & 4095;
            int r1g = m0 + rhi, bb1 = r1g >> 12, t1 = r1g & 4095;
            g_vT[(size_t)bb0 * 262144 + (size_t)hh * 4096 + t0]       = e0;
            g_vT[(size_t)bb0 * 262144 + (size_t)(hh + 1) * 4096 + t0] = e1;
            g_vT[(size_t)bb1 * 262144 + (size_t)hh * 4096 + t1]       = e2;
            g_vT[(size_t)bb1 * 262144 + (size_t)(hh + 1) * 4096 + t1] = e3;
        }
    }
}

// ---------------------------------------------------------------------------
// Flash attention (causal), n-half SPLIT-K flash. 256 thr = 8 warps.
// Warp (rg = wid&3, nh = wid>>2): rows rg*16..+15, keys nh*32..+31 of each
// 64-key tile. Each warp runs an independent online softmax over its key-half
// (private m,l,O; warp-local quad-shuffle reductions; register-resident P via
// quad permute). The two nh-groups are merged ONCE per side via smem overlay:
//   O = (O0*e^{m0-M} + O1*e^{m1-M}) / (l0*e^{m0-M} + l1*e^{m1-M}).
// An all-masked half keeps m=-1e30 -> combine weight exp(-1e30-M)=0 kills its
// garbage contribution exactly. One __syncthreads per tile (KV publish).
// AS=68: 2*AS mod 32 == 8 -> uint2 frag loads are bank-conflict-free.
// Pair schedule (i, 63-i): 65 tiles per block. Grid (32, B).
// ---------------------------------------------------------------------------
#define AS 68    // float2 row stride (conflict-free for uint2 frag loads)
#define OST 72   // float stride for combine overlay (8g+2tig banks, c-free)

__device__ __forceinline__ void issue_kv(const float2* kb, const float2* vb,
                                         int jt, float2* Ks, float2* Vt, int tid)
{
#pragma unroll
    for (int i = 0; i < 8; i++) {
        int c = tid + i * 256;            // 0..2047
        int r = c >> 5, q = c & 31;
        cp16(sptr(Ks + r * AS + q * 2), kb + (size_t)(jt * 64 + r) * 64 + q * 2);
        cp16(sptr(Vt + r * AS + q * 2), vb + (size_t)r * 4096 + jt * 64 + q * 2);
    }
}

__global__ __launch_bounds__(256)
void attn_kernel(float* __restrict__ out)
{
    extern __shared__ float2 smp[];
    float2* Ks0 = smp;
    float2* Vt0 = Ks0 + 64 * AS;
    float2* Ks1 = Vt0 + 64 * AS;
    float2* Vt1 = Ks1 + 64 * AS;
    float*  Osm = (float*)Ks1;            // combine overlay: [64][OST] floats
    float*  msm = (float*)Vt1;            // [64]
    float*  lsm = msm + 64;               // [64]

    const int b    = blockIdx.y;
    const int pair = blockIdx.x;
    const int tid  = threadIdx.x;
    const int wid  = tid >> 5;
    const int lane = tid & 31;
    const int g    = lane >> 2;
    const int tig  = lane & 3;
    const int rg   = wid & 3;
    const int nh   = wid >> 2;            // key half: 0 or 1
    const int kB   = nh * 32;             // key base within tile
    const int rlo  = rg * 16 + g;
    const int rhi  = rlo + 8;
    const int src0 = (lane & 28) | (tig >> 1);
    const int src1 = src0 + 2;

    const float2* kb = g_khl + (size_t)b * T_ * 64;
    const float2* vb = g_vT  + (size_t)b * 64 * T_;
    const float2* qb = g_qhl + (size_t)b * T_ * 64;

    for (int side = 0; side < 2; side++) {
        const int qt = side ? (63 - pair) : pair;
        const int q0 = qt * 64;
        const int ntile = qt + 1;

        __syncthreads();   // prior side's smem consumers (incl. combine) done

        // Q fragments straight from gmem
        uint32_t qhi[8][4], qlo[8][4];
        {
            const uint2* qr0 = (const uint2*)(qb + (size_t)(q0 + rlo) * 64);
            const uint2* qr1 = (const uint2*)(qb + (size_t)(q0 + rhi) * 64);
#pragma unroll
            for (int i = 0; i < 8; i++) {
                uint2 t;
                t = qr0[8 * i + tig];     qhi[i][0] = t.x; qlo[i][0] = t.y;
                t = qr1[8 * i + tig];     qhi[i][1] = t.x; qlo[i][1] = t.y;
                t = qr0[8 * i + tig + 4]; qhi[i][2] = t.x; qlo[i][2] = t.y;
                t = qr1[8 * i + tig + 4]; qhi[i][3] = t.x; qlo[i][3] = t.y;
            }
        }

        issue_kv(kb, vb, 0, Ks0, Vt0, tid);
        CP_COMMIT();

        float mA = -CUDART_INF_F, mB = -CUDART_INF_F;   // row rlo / rhi
        float lA = 0.f, lB = 0.f;
        float o[8][4];
#pragma unroll
        for (int f = 0; f < 8; f++)
#pragma unroll
            for (int j = 0; j < 4; j++) o[f][j] = 0.f;

        for (int jt = 0; jt < ntile; jt++) {
            CP_WAIT0();
            __syncthreads();   // KV[jt&1] visible; other buffer free

            const float2* Kst = (jt & 1) ? Ks1 : Ks0;
            const float2* Vtt = (jt & 1) ? Vt1 : Vt0;
            if (jt + 1 < ntile) {
                issue_kv(kb, vb, jt + 1, (jt & 1) ? Ks0 : Ks1,
                         (jt & 1) ? Vt0 : Vt1, tid);
                CP_COMMIT();
            }

            // ---- S = Q.K^T (3xTF32), warp tile m16 x n32 (own key half)
            float s[4][4];
#pragma unroll
            for (int f = 0; f < 4; f++)
#pragma unroll
                for (int j = 0; j < 4; j++) s[f][j] = 0.f;

#pragma unroll
            for (int i = 0; i < 8; i++) {
#pragma unroll
                for (int f = 0; f < 4; f++) {
                    uint2 u0 = *(const uint2*)&Kst[(kB + 8 * f + g) * AS + 8 * i + tig];
                    uint2 u1 = *(const uint2*)&Kst[(kB + 8 * f + g) * AS + 8 * i + tig + 4];
                    mma8(s[f], qhi[i], u0.x, u1.x);
                    mma8(s[f], qhi[i], u0.y, u1.y);
                    mma8(s[f], qlo[i], u0.x, u1.x);
                }
            }

            // ---- causal mask (diagonal tile only)
            if (jt == ntile - 1) {
                const int rglo = q0 + rlo, rghi = q0 + rhi;
                const int cb = jt * 64 + kB;
#pragma unroll
                for (int f = 0; f < 4; f++) {
                    int c0 = cb + 8 * f + 2 * tig;
                    if (c0 > rglo)     s[f][0] = -1e30f;
                    if (c0 + 1 > rglo) s[f][1] = -1e30f;
                    if (c0 > rghi)     s[f][2] = -1e30f;
                    if (c0 + 1 > rghi) s[f][3] = -1e30f;
                }
            }

            // ---- warp-local row max over this key half
            float pmA = -CUDART_INF_F, pmB = -CUDART_INF_F;
#pragma unroll
            for (int f = 0; f < 4; f++) {
                pmA = fmaxf(pmA, fmaxf(s[f][0], s[f][1]));
                pmB = fmaxf(pmB, fmaxf(s[f][2], s[f][3]));
            }
            pmA = fmaxf(pmA, __shfl_xor_sync(0xffffffffu, pmA, 1));
            pmA = fmaxf(pmA, __shfl_xor_sync(0xffffffffu, pmA, 2));
            pmB = fmaxf(pmB, __shfl_xor_sync(0xffffffffu, pmB, 1));
            pmB = fmaxf(pmB, __shfl_xor_sync(0xffffffffu, pmB, 2));

            const float mnA = fmaxf(mA, pmA);
            const float mnB = fmaxf(mB, pmB);
            const float aA  = __expf(mA - mnA);
            const float aB  = __expf(mB - mnB);
            mA = mnA; mB = mnB;

            // ---- p = exp(s - m), partial l, rescale O
            float psA = 0.f, psB = 0.f;
#pragma unroll
            for (int f = 0; f < 4; f++) {
                s[f][0] = __expf(s[f][0] - mnA);
                s[f][1] = __expf(s[f][1] - mnA);
                s[f][2] = __expf(s[f][2] - mnB);
                s[f][3] = __expf(s[f][3] - mnB);
                psA += s[f][0] + s[f][1];
                psB += s[f][2] + s[f][3];
            }
            psA += __shfl_xor_sync(0xffffffffu, psA, 1);
            psA += __shfl_xor_sync(0xffffffffu, psA, 2);
            psB += __shfl_xor_sync(0xffffffffu, psB, 1);
            psB += __shfl_xor_sync(0xffffffffu, psB, 2);
            lA = lA * aA + psA;
            lB = lB * aB + psB;
#pragma unroll
            for (int f = 0; f < 8; f++) {
                o[f][0] *= aA; o[f][1] *= aA;
                o[f][2] *= aB; o[f][3] *= aB;
            }

            // ---- O += P.V (2-term), P permuted C->A via quad shuffles.
            // k range = this warp's 32 keys: 4 k8-chunks from s[f].
#pragma unroll
            for (int f = 0; f < 4; f++) {
                uint32_t u0 = cvt_tf32(s[f][0]);
                uint32_t u1 = cvt_tf32(s[f][1]);
                uint32_t u2 = cvt_tf32(s[f][2]);
                uint32_t u3 = cvt_tf32(s[f][3]);
                uint32_t pa[4];
                {
                    uint32_t x0 = __shfl_sync(0xffffffffu, u0, src0);
                    uint32_t x1 = __shfl_sync(0xffffffffu, u1, src0);
                    pa[0] = (tig & 1) ? x1 : x0;
                    uint32_t y0 = __shfl_sync(0xffffffffu, u2, src0);
                    uint32_t y1 = __shfl_sync(0xffffffffu, u3, src0);
                    pa[1] = (tig & 1) ? y1 : y0;
                    uint32_t z0 = __shfl_sync(0xffffffffu, u0, src1);
                    uint32_t z1 = __shfl_sync(0xffffffffu, u1, src1);
                    pa[2] = (tig & 1) ? z1 : z0;
                    uint32_t w0 = __shfl_sync(0xffffffffu, u2, src1);
                    uint32_t w1 = __shfl_sync(0xffffffffu, u3, src1);
                    pa[3] = (tig & 1) ? w1 : w0;
                }
#pragma unroll
                for (int fo = 0; fo < 8; fo++) {
                    uint2 v0 = *(const uint2*)&Vtt[(8 * fo + g) * AS + kB + 8 * f + tig];
                    uint2 v1 = *(const uint2*)&Vtt[(8 * fo + g) * AS + kB + 8 * f + tig + 4];
                    mma8(o[fo], pa, v0.x, v1.x);
                    mma8(o[fo], pa, v0.y, v1.y);
                }
            }
        }

        // ---- combine the two key-half groups, write output
        __syncthreads();   // all KV reads done; safe to overlay Ks1/Vt1
        if (nh == 1) {
#pragma unroll
            for (int f = 0; f < 8; f++) {
                int cc = 8 * f + 2 * tig;
                *(float2*)&Osm[rlo * OST + cc] = make_float2(o[f][0], o[f][1]);
                *(float2*)&Osm[rhi * OST + cc] = make_float2(o[f][2], o[f][3]);
            }
            if (tig == 0) {
                msm[rlo] = mA; lsm[rlo] = lA;
                msm[rhi] = mB; lsm[rhi] = lB;
            }
        }
        __syncthreads();
        if (nh == 0) {
            const float m1A = msm[rlo], l1A = lsm[rlo];
            const float m1B = msm[rhi], l1B = lsm[rhi];
            const float MA = fmaxf(mA, m1A), MB = fmaxf(mB, m1B);
            const float w0A = __expf(mA - MA),  w1A = __expf(m1A - MA);
            const float w0B = __expf(mB - MB),  w1B = __expf(m1B - MB);
            const float invA = 1.f / (lA * w0A + l1A * w1A);
            const float invB = 1.f / (lB * w0B + l1B * w1B);
            float* or0 = out + ((size_t)b * T_ + q0 + rlo) * H_;
            float* or1 = out + ((size_t)b * T_ + q0 + rhi) * H_;
#pragma unroll
            for (int f = 0; f < 8; f++) {
                int cc = 8 * f + 2 * tig;
                float2 p0 = *(const float2*)&Osm[rlo * OST + cc];
                float2 p1 = *(const float2*)&Osm[rhi * OST + cc];
                *(float2*)&or0[cc] = make_float2(
                    (o[f][0] * w0A + p0.x * w1A) * invA,
                    (o[f][1] * w0A + p0.y * w1A) * invA);
                *(float2*)&or1[cc] = make_float2(
                    (o[f][2] * w0B + p1.x * w1B) * invB,
                    (o[f][3] * w0B + p1.y * w1B) * invB);
            }
        }
    }
}

// ---------------------------------------------------------------------------

extern "C" void kernel_launch(void* const* d_in, const int* in_sizes, int n_in,
                              void* d_out, int out_size)
{
    const float* x  = (const float*)d_in[0];
    const float* Wk = (const float*)d_in[1];
    const float* Wq = (const float*)d_in[2];
    const float* Wv = (const float*)d_in[3];
    float* out = (float*)d_out;

    prep_w<<<768, 256>>>(Wq, Wk, Wv);

    const int psmem = (2 * 128 * PW + 2 * 192 * PW) * (int)sizeof(float2); // 174080
    cudaFuncSetAttribute(proj_kernel, cudaFuncAttributeMaxDynamicSharedMemorySize, psmem);
    proj_kernel<<<128, 256, psmem>>>(x);

    const int asmem = 4 * 64 * AS * (int)sizeof(float2); // 139264
    cudaFuncSetAttribute(attn_kernel, cudaFuncAttributeMaxDynamicSharedMemorySize, asmem);
    attn_kernel<<<dim3(32, B_), 256, asmem>>>(out);
}